// round 9
// baseline (speedup 1.0000x reference)
#include <cuda_runtime.h>
#include <cuda_fp16.h>

// CPDecoding: out[n] = sum_c prod_d lerp(line_coef[d][c], pos_d(n))
// coords stacked (z,y,x): table dim d uses input column (2-d).
//
// R9 = R8 body (fp16 diff table: one 128-B row per point-dim -> exactly one
// LDS.128 wavefront; HFMA2 lerp + half2 d0*d1 product, fp32 finish; no
// clamps; pipelined coord loads; fused A/B reduction; 8 pts/warp-iter)
// at 640 thr x 2 CTAs/SM (296 CTAs): 40 warps/SM vs 32, reg cap 51.
// R8 ncu: L1 77.5% busy vs a 36-wf/iter MIO floor (~36.5us) -> 22% latency
// exposure is the entire remaining gap; 2x96KB smem fits, and the 61->51
// reg squeeze is mild (R6's failure was 768x2 forcing 40 regs).

#define NCOMP 24
#define RES   256
#define ROWU2 16                        // uint2 slots per row (12 data + 4 pad)
#define TAB_U2 (3 * RES * ROWU2)        // 12288 uint2 = 98304 B

#define THREADS 640
#define NCTAS   296                     // 2 per SM

__global__ __launch_bounds__(THREADS, 2)
void cp_decode_kernel(const float* __restrict__ pts,
                      const float* __restrict__ coef,
                      float* __restrict__ out,
                      int npts)
{
    extern __shared__ uint2 tabu2[];

    // ---- Build fp16 diff table ----
    const int tid = threadIdx.x;
    for (int e = tid; e < TAB_U2; e += THREADS) {
        int d   = e / (RES * ROWU2);
        int rem = e - d * (RES * ROWU2);
        int i   = rem / ROWU2;
        int j   = rem - i * ROWU2;
        uint2 val = make_uint2(0u, 0u);
        if (j < 12) {
            const float* ca = coef + (d * NCOMP + 2 * j) * RES;
            const float* cb = ca + RES;
            float a0 = __ldg(ca + i);
            float a1 = (i < RES - 1) ? __ldg(ca + i + 1) : a0;
            float b0 = __ldg(cb + i);
            float b1 = (i < RES - 1) ? __ldg(cb + i + 1) : b0;
            __half2 f0 = __floats2half2_rn(a0, b0);
            __half2 df = __floats2half2_rn(a1 - a0, b1 - b0);
            val.x = *reinterpret_cast<unsigned*>(&f0);
            val.y = *reinterpret_cast<unsigned*>(&df);
        }
        tabu2[e] = val;
    }
    __syncthreads();

    const uint4* __restrict__ tab4 = reinterpret_cast<const uint4*>(tabu2);

    const int lane   = tid & 31;
    const int gwarp  = (blockIdx.x * THREADS + tid) >> 5;
    const int nwarps = (NCTAS * THREADS) >> 5;

    const int p   = lane >> 3;       // point slot in group of 4
    const int sub = lane & 7;        // lane within point (comps 4sub..4sub+3)

    const int nfull = npts >> 3;     // full 8-point iterations (all in-bounds)

    // Prologue: stage first iteration's 24 coords on lanes 0..23.
    int iter = gwarp;
    float v = 0.0f;
    if (iter < nfull && lane < 24)
        v = __ldg(pts + iter * 24 + lane);

    for (; iter < nfull; iter += nwarps) {
        const int base = iter << 3;

        // Per-dim sample index + weight for both groups. pos in [127.5,255)
        // for coords in [0,1) -> no clamping needed.
        int   iA[3], iB[3];
        float wAf[3], wBf[3];
        #pragma unroll
        for (int d = 0; d < 3; d++) {
            float xA = __shfl_sync(0xffffffffu, v, p * 3 + (2 - d));
            float xB = __shfl_sync(0xffffffffu, v, 12 + p * 3 + (2 - d));
            float posA = fmaf(xA, 127.5f, 127.5f);
            float posB = fmaf(xB, 127.5f, 127.5f);
            int ia = __float2int_rd(posA);
            int ib = __float2int_rd(posB);
            wAf[d] = posA - (float)ia;
            wBf[d] = posB - (float)ib;
            iA[d] = ia;
            iB[d] = ib;
        }

        // Prefetch next iteration's coords.
        float vn = 0.0f;
        {
            int itn = iter + nwarps;
            if (itn < nfull && lane < 24)
                vn = __ldg(pts + itn * 24 + lane);
        }

        // ---- group A ----
        float accA;
        {
            __half2 LA[3], LB[3];
            #pragma unroll
            for (int d = 0; d < 3; d++) {
                uint4 q = tab4[(d * RES + iA[d]) * 8 + sub];
                __half2 w2  = __float2half2_rn(wAf[d]);
                __half2 f0a = *reinterpret_cast<__half2*>(&q.x);
                __half2 dfa = *reinterpret_cast<__half2*>(&q.y);
                __half2 f0b = *reinterpret_cast<__half2*>(&q.z);
                __half2 dfb = *reinterpret_cast<__half2*>(&q.w);
                LA[d] = __hfma2(w2, dfa, f0a);
                LB[d] = __hfma2(w2, dfb, f0b);
            }
            float2 pa = __half22float2(__hmul2(LA[0], LA[1]));  // half product d0*d1
            float2 pb = __half22float2(__hmul2(LB[0], LB[1]));
            float2 la = __half22float2(LA[2]);                  // third factor
            float2 lb = __half22float2(LB[2]);
            float t0 = pa.x * la.x;
            float t1 = fmaf(pa.y, la.y, t0);
            float t2 = fmaf(pb.x, lb.x, t1);
            accA     = fmaf(pb.y, lb.y, t2);
        }

        // ---- group B ----
        float accB;
        {
            __half2 LA[3], LB[3];
            #pragma unroll
            for (int d = 0; d < 3; d++) {
                uint4 q = tab4[(d * RES + iB[d]) * 8 + sub];
                __half2 w2  = __float2half2_rn(wBf[d]);
                __half2 f0a = *reinterpret_cast<__half2*>(&q.x);
                __half2 dfa = *reinterpret_cast<__half2*>(&q.y);
                __half2 f0b = *reinterpret_cast<__half2*>(&q.z);
                __half2 dfb = *reinterpret_cast<__half2*>(&q.w);
                LA[d] = __hfma2(w2, dfa, f0a);
                LB[d] = __hfma2(w2, dfb, f0b);
            }
            float2 pa = __half22float2(__hmul2(LA[0], LA[1]));
            float2 pb = __half22float2(__hmul2(LB[0], LB[1]));
            float2 la = __half22float2(LA[2]);
            float2 lb = __half22float2(LB[2]);
            float t0 = pa.x * la.x;
            float t1 = fmaf(pa.y, la.y, t0);
            float t2 = fmaf(pb.x, lb.x, t1);
            accB     = fmaf(pb.y, lb.y, t2);
        }

        // Fused A/B reduction: xor4 merges groups, xor2/xor1 finish quads.
        // Lane p*8+0 ends with sumA, lane p*8+4 with sumB.
        {
            float uA = __shfl_xor_sync(0xffffffffu, accA, 4);
            float uB = __shfl_xor_sync(0xffffffffu, accB, 4);
            float m  = (sub < 4) ? (accA + uA) : (accB + uB);
            m += __shfl_xor_sync(0xffffffffu, m, 2);
            m += __shfl_xor_sync(0xffffffffu, m, 1);
            if ((sub & 3) == 0)
                out[base + p + (sub & 4)] = m;   // sub==0 -> A, sub==4 -> B
        }

        v = vn;
    }

    // ---- scalar tail: npts % 8 leftover points, handled by warp 0 ----
    const int rem = npts & 7;
    if (rem && gwarp == 0 && lane < rem) {
        int n = (npts & ~7) + lane;
        float acc = 0.0f;
        int   idx[3];
        float wd[3];
        #pragma unroll
        for (int d = 0; d < 3; d++) {
            float x = pts[n * 3 + (2 - d)];
            float pos = fmaf(x, 127.5f, 127.5f);
            int i = __float2int_rd(pos);
            i = min(max(i, 0), RES - 1);
            idx[d] = i;
            wd[d] = pos - (float)i;
        }
        for (int c = 0; c < NCOMP; c++) {
            float prod = 1.0f;
            #pragma unroll
            for (int d = 0; d < 3; d++) {
                uint2 q = tabu2[(d * RES + idx[d]) * ROWU2 + (c >> 1)];
                __half2 f0 = *reinterpret_cast<__half2*>(&q.x);
                __half2 df = *reinterpret_cast<__half2*>(&q.y);
                float2 f0f = __half22float2(f0);
                float2 dff = __half22float2(df);
                float a = (c & 1) ? f0f.y : f0f.x;
                float b = (c & 1) ? dff.y : dff.x;
                prod *= fmaf(wd[d], b, a);
            }
            acc += prod;
        }
        out[n] = acc;
    }
}

extern "C" void kernel_launch(void* const* d_in, const int* in_sizes, int n_in,
                              void* d_out, int out_size)
{
    const float* pts  = (const float*)d_in[0];   // [N,3] float32
    const float* coef = (const float*)d_in[1];   // [3,24,256] float32
    float* out = (float*)d_out;

    const int npts = in_sizes[0] / 3;
    const size_t smem = TAB_U2 * sizeof(uint2);  // 98304 B

    cudaFuncSetAttribute(cp_decode_kernel,
                         cudaFuncAttributeMaxDynamicSharedMemorySize,
                         (int)smem);

    cp_decode_kernel<<<NCTAS, THREADS, smem>>>(pts, coef, out, npts);
}

// round 11
// speedup vs baseline: 1.2063x; 1.2063x over previous
#include <cuda_runtime.h>
#include <cuda_fp16.h>

// CPDecoding: out[n] = sum_c prod_d lerp(line_coef[d][c], pos_d(n))
// coords stacked (z,y,x): table dim d uses input column (2-d).
//
// R11 = R8 body (LOCKED: 1024 thr x 148 CTAs, 1 CTA/SM; fp16 diff table,
// one 128-B row per point-dim -> one LDS.128 wavefront; HFMA2 lerp + half2
// d0*d1 product, fp32 finish; no clamps; pipelined coord loads; fused A/B
// shfl reduction) + the two safe R10 changes:
//  - build diet: pad zero-fill split into pure-STS rounds; data build runs
//    9 rounds instead of 12, each carrying 4 scattered LDGs.
//  - prologue coord LDG hoisted above the table build (DRAM latency hidden
//    under build + __syncthreads).
// R10 lesson: redux.sync.add.f32 does NOT exist on sm_103 -- shfl tree only.

#define NCOMP 24
#define RES   256
#define ROWU2 16                        // uint2 slots per row (12 data + 4 pad)
#define TAB_U2 (3 * RES * ROWU2)        // 12288 uint2 = 98304 B
#define NDATA  (3 * RES * 12)           // 9216 data entries

#define THREADS 1024
#define NCTAS   148

__global__ __launch_bounds__(THREADS, 1)
void cp_decode_kernel(const float* __restrict__ pts,
                      const float* __restrict__ coef,
                      float* __restrict__ out,
                      int npts)
{
    extern __shared__ uint2 tabu2[];

    const int tid    = threadIdx.x;
    const int lane   = tid & 31;
    const int gwarp  = (blockIdx.x * THREADS + tid) >> 5;
    const int nwarps = (NCTAS * THREADS) >> 5;
    const int nfull  = npts >> 3;    // full 8-point iterations (all in-bounds)

    // Prologue coord load issued BEFORE the build: latency hidden under it.
    int iter = gwarp;
    float v = 0.0f;
    if (iter < nfull && lane < 24)
        v = __ldg(pts + iter * 24 + lane);

    // ---- Zero the pad slots (j = 12..15 of each row): pure STS ----
    for (int e = tid; e < 3 * RES * 4; e += THREADS) {
        int row = e >> 2;
        int jj  = e & 3;
        tabu2[row * ROWU2 + 12 + jj] = make_uint2(0u, 0u);
    }

    // ---- Build fp16 diff table (data slots only, 9 rounds) ----
    for (int e = tid; e < NDATA; e += THREADS) {
        int d   = e / (RES * 12);
        int rem = e - d * (RES * 12);
        int i   = rem / 12;
        int j   = rem - i * 12;
        const float* ca = coef + (d * NCOMP + 2 * j) * RES;
        const float* cb = ca + RES;
        float a0 = __ldg(ca + i);
        float a1 = (i < RES - 1) ? __ldg(ca + i + 1) : a0;
        float b0 = __ldg(cb + i);
        float b1 = (i < RES - 1) ? __ldg(cb + i + 1) : b0;
        __half2 f0 = __floats2half2_rn(a0, b0);
        __half2 df = __floats2half2_rn(a1 - a0, b1 - b0);
        uint2 val;
        val.x = *reinterpret_cast<unsigned*>(&f0);
        val.y = *reinterpret_cast<unsigned*>(&df);
        tabu2[(d * RES + i) * ROWU2 + j] = val;
    }
    __syncthreads();

    const uint4* __restrict__ tab4 = reinterpret_cast<const uint4*>(tabu2);

    const int p   = lane >> 3;       // point slot in group of 4
    const int sub = lane & 7;        // lane within point (comps 4sub..4sub+3)

    for (; iter < nfull; iter += nwarps) {
        const int base = iter << 3;

        // Per-dim sample index + weight for both groups. pos in [127.5,255)
        // for coords in [0,1) -> no clamping needed.
        int   iA[3], iB[3];
        float wAf[3], wBf[3];
        #pragma unroll
        for (int d = 0; d < 3; d++) {
            float xA = __shfl_sync(0xffffffffu, v, p * 3 + (2 - d));
            float xB = __shfl_sync(0xffffffffu, v, 12 + p * 3 + (2 - d));
            float posA = fmaf(xA, 127.5f, 127.5f);
            float posB = fmaf(xB, 127.5f, 127.5f);
            int ia = __float2int_rd(posA);
            int ib = __float2int_rd(posB);
            wAf[d] = posA - (float)ia;
            wBf[d] = posB - (float)ib;
            iA[d] = ia;
            iB[d] = ib;
        }

        // Prefetch next iteration's coords.
        float vn = 0.0f;
        {
            int itn = iter + nwarps;
            if (itn < nfull && lane < 24)
                vn = __ldg(pts + itn * 24 + lane);
        }

        // ---- group A ----
        float accA;
        {
            __half2 LA[3], LB[3];
            #pragma unroll
            for (int d = 0; d < 3; d++) {
                uint4 q = tab4[(d * RES + iA[d]) * 8 + sub];
                __half2 w2  = __float2half2_rn(wAf[d]);
                __half2 f0a = *reinterpret_cast<__half2*>(&q.x);
                __half2 dfa = *reinterpret_cast<__half2*>(&q.y);
                __half2 f0b = *reinterpret_cast<__half2*>(&q.z);
                __half2 dfb = *reinterpret_cast<__half2*>(&q.w);
                LA[d] = __hfma2(w2, dfa, f0a);
                LB[d] = __hfma2(w2, dfb, f0b);
            }
            float2 pa = __half22float2(__hmul2(LA[0], LA[1]));  // half product d0*d1
            float2 pb = __half22float2(__hmul2(LB[0], LB[1]));
            float2 la = __half22float2(LA[2]);                  // third factor
            float2 lb = __half22float2(LB[2]);
            float t0 = pa.x * la.x;
            float t1 = fmaf(pa.y, la.y, t0);
            float t2 = fmaf(pb.x, lb.x, t1);
            accA     = fmaf(pb.y, lb.y, t2);
        }

        // ---- group B ----
        float accB;
        {
            __half2 LA[3], LB[3];
            #pragma unroll
            for (int d = 0; d < 3; d++) {
                uint4 q = tab4[(d * RES + iB[d]) * 8 + sub];
                __half2 w2  = __float2half2_rn(wBf[d]);
                __half2 f0a = *reinterpret_cast<__half2*>(&q.x);
                __half2 dfa = *reinterpret_cast<__half2*>(&q.y);
                __half2 f0b = *reinterpret_cast<__half2*>(&q.z);
                __half2 dfb = *reinterpret_cast<__half2*>(&q.w);
                LA[d] = __hfma2(w2, dfa, f0a);
                LB[d] = __hfma2(w2, dfb, f0b);
            }
            float2 pa = __half22float2(__hmul2(LA[0], LA[1]));
            float2 pb = __half22float2(__hmul2(LB[0], LB[1]));
            float2 la = __half22float2(LA[2]);
            float2 lb = __half22float2(LB[2]);
            float t0 = pa.x * la.x;
            float t1 = fmaf(pa.y, la.y, t0);
            float t2 = fmaf(pb.x, lb.x, t1);
            accB     = fmaf(pb.y, lb.y, t2);
        }

        // Fused A/B reduction: xor4 merges groups, xor2/xor1 finish quads.
        // Lane p*8+0 ends with sumA, lane p*8+4 with sumB.
        {
            float uA = __shfl_xor_sync(0xffffffffu, accA, 4);
            float uB = __shfl_xor_sync(0xffffffffu, accB, 4);
            float m  = (sub < 4) ? (accA + uA) : (accB + uB);
            m += __shfl_xor_sync(0xffffffffu, m, 2);
            m += __shfl_xor_sync(0xffffffffu, m, 1);
            if ((sub & 3) == 0)
                out[base + p + (sub & 4)] = m;   // sub==0 -> A, sub==4 -> B
        }

        v = vn;
    }

    // ---- scalar tail: npts % 8 leftover points, handled by warp 0 ----
    const int rem = npts & 7;
    if (rem && gwarp == 0 && lane < rem) {
        int n = (npts & ~7) + lane;
        float acc = 0.0f;
        int   idx[3];
        float wd[3];
        #pragma unroll
        for (int d = 0; d < 3; d++) {
            float x = pts[n * 3 + (2 - d)];
            float pos = fmaf(x, 127.5f, 127.5f);
            int i = __float2int_rd(pos);
            i = min(max(i, 0), RES - 1);
            idx[d] = i;
            wd[d] = pos - (float)i;
        }
        for (int c = 0; c < NCOMP; c++) {
            float prod = 1.0f;
            #pragma unroll
            for (int d = 0; d < 3; d++) {
                uint2 q = tabu2[(d * RES + idx[d]) * ROWU2 + (c >> 1)];
                __half2 f0 = *reinterpret_cast<__half2*>(&q.x);
                __half2 df = *reinterpret_cast<__half2*>(&q.y);
                float2 f0f = __half22float2(f0);
                float2 dff = __half22float2(df);
                float a = (c & 1) ? f0f.y : f0f.x;
                float b = (c & 1) ? dff.y : dff.x;
                prod *= fmaf(wd[d], b, a);
            }
            acc += prod;
        }
        out[n] = acc;
    }
}

extern "C" void kernel_launch(void* const* d_in, const int* in_sizes, int n_in,
                              void* d_out, int out_size)
{
    const float* pts  = (const float*)d_in[0];   // [N,3] float32
    const float* coef = (const float*)d_in[1];   // [3,24,256] float32
    float* out = (float*)d_out;

    const int npts = in_sizes[0] / 3;
    const size_t smem = TAB_U2 * sizeof(uint2);  // 98304 B

    cudaFuncSetAttribute(cp_decode_kernel,
                         cudaFuncAttributeMaxDynamicSharedMemorySize,
                         (int)smem);

    cp_decode_kernel<<<NCTAS, THREADS, smem>>>(pts, coef, out, npts);
}

// round 12
// speedup vs baseline: 1.3075x; 1.0839x over previous
#include <cuda_runtime.h>
#include <cuda_fp16.h>

// CPDecoding: out[n] = sum_c prod_d lerp(line_coef[d][c], pos_d(n))
// coords stacked (z,y,x): table dim d uses input column (2-d).
//
// R12 = R11 mainloop (LOCKED: 1024 thr x 148 CTAs, 1 CTA/SM; fp16 diff
// table, one 128-B row per point-dim -> one LDS.128 wavefront; HFMA2 lerp +
// half2 d0*d1 product, fp32 finish; no clamps; pipelined coord loads) with:
//  - Coalesced build: warp-per-(d, 32-row block), lane = row. All 48 LDGs
//    lane-consecutive over i (1-2 wf/instr vs ~20 for the old strided-1024
//    pattern). STS 128-B row stride is bank-degenerate, so rows are stored
//    with an XOR slot swizzle: slot m of row i lives at position m ^ (i&7)
//    -> build STS conflict 32-way -> 4-way. Mainloop reads sub ^ (i&7)
//    (self-inverse; component alignment across dims preserved).
//  - 3-shfl fused reduction (select-exchange-select replaces one xor4 pair);
//    identical summation tree -> bit-identical output.

#define NCOMP 24
#define RES   256
#define ROWU2 16                        // uint2 slots per row (6 data + 2 pad uint4)
#define TAB_U2 (3 * RES * ROWU2)        // 12288 uint2 = 98304 B

#define THREADS 1024
#define NCTAS   148

__global__ __launch_bounds__(THREADS, 1)
void cp_decode_kernel(const float* __restrict__ pts,
                      const float* __restrict__ coef,
                      float* __restrict__ out,
                      int npts)
{
    extern __shared__ uint2 tabu2[];
    uint4* __restrict__ tabw = reinterpret_cast<uint4*>(tabu2);

    const int tid    = threadIdx.x;
    const int lane   = tid & 31;
    const int wid    = tid >> 5;
    const int gwarp  = (blockIdx.x * THREADS + tid) >> 5;
    const int nwarps = (NCTAS * THREADS) >> 5;
    const int nfull  = npts >> 3;    // full 8-point iterations (all in-bounds)

    // Prologue coord load issued BEFORE the build: latency hidden under it.
    int iter = gwarp;
    float v = 0.0f;
    if (iter < nfull && lane < 24)
        v = __ldg(pts + iter * 24 + lane);

    // ---- Build fp16 diff table: warp-per-(d, 32-row block), coalesced ----
    // Row i layout: 8 uint4 positions; data slot m (comps 4m..4m+3) stored at
    // position m ^ (i&7); positions of slots 6,7 hold zeros.
    if (wid < 24) {
        const int d = wid >> 3;
        const int i = ((wid & 7) << 5) | lane;
        const float* cbase = coef + d * (NCOMP * RES) + i;
        const int ip = (i < RES - 1) ? 1 : 0;
        uint4 s[6];
        #pragma unroll
        for (int h = 0; h < 6; h++) {          // slot h = comps 4h..4h+3
            float a0 = __ldg(cbase + (4 * h + 0) * RES);
            float a1 = __ldg(cbase + (4 * h + 0) * RES + ip);
            float b0 = __ldg(cbase + (4 * h + 1) * RES);
            float b1 = __ldg(cbase + (4 * h + 1) * RES + ip);
            float c0 = __ldg(cbase + (4 * h + 2) * RES);
            float c1 = __ldg(cbase + (4 * h + 2) * RES + ip);
            float e0 = __ldg(cbase + (4 * h + 3) * RES);
            float e1 = __ldg(cbase + (4 * h + 3) * RES + ip);
            __half2 f0x = __floats2half2_rn(a0, b0);
            __half2 dfx = __floats2half2_rn(a1 - a0, b1 - b0);
            __half2 f0y = __floats2half2_rn(c0, e0);
            __half2 dfy = __floats2half2_rn(c1 - c0, e1 - e0);
            s[h].x = *reinterpret_cast<unsigned*>(&f0x);
            s[h].y = *reinterpret_cast<unsigned*>(&dfx);
            s[h].z = *reinterpret_cast<unsigned*>(&f0y);
            s[h].w = *reinterpret_cast<unsigned*>(&dfy);
        }
        uint4* row = tabw + ((d * RES + i) << 3);
        const int sw = i & 7;
        #pragma unroll
        for (int m = 0; m < 6; m++)
            row[m ^ sw] = s[m];
        row[6 ^ sw] = make_uint4(0u, 0u, 0u, 0u);
        row[7 ^ sw] = make_uint4(0u, 0u, 0u, 0u);
    }
    __syncthreads();

    const uint4* __restrict__ tab4 = tabw;

    const int p   = lane >> 3;       // point slot in group of 4
    const int sub = lane & 7;        // lane within point (comps 4sub..4sub+3)

    for (; iter < nfull; iter += nwarps) {
        const int base = iter << 3;

        // Per-dim sample index + weight for both groups. pos in [127.5,255)
        // for coords in [0,1) -> no clamping needed.
        int   iA[3], iB[3];
        float wAf[3], wBf[3];
        #pragma unroll
        for (int d = 0; d < 3; d++) {
            float xA = __shfl_sync(0xffffffffu, v, p * 3 + (2 - d));
            float xB = __shfl_sync(0xffffffffu, v, 12 + p * 3 + (2 - d));
            float posA = fmaf(xA, 127.5f, 127.5f);
            float posB = fmaf(xB, 127.5f, 127.5f);
            int ia = __float2int_rd(posA);
            int ib = __float2int_rd(posB);
            wAf[d] = posA - (float)ia;
            wBf[d] = posB - (float)ib;
            iA[d] = ia;
            iB[d] = ib;
        }

        // Prefetch next iteration's coords.
        float vn = 0.0f;
        {
            int itn = iter + nwarps;
            if (itn < nfull && lane < 24)
                vn = __ldg(pts + itn * 24 + lane);
        }

        // ---- group A ----
        float accA;
        {
            __half2 LA[3], LB[3];
            #pragma unroll
            for (int d = 0; d < 3; d++) {
                uint4 q = tab4[((d * RES + iA[d]) << 3) + (sub ^ (iA[d] & 7))];
                __half2 w2  = __float2half2_rn(wAf[d]);
                __half2 f0a = *reinterpret_cast<__half2*>(&q.x);
                __half2 dfa = *reinterpret_cast<__half2*>(&q.y);
                __half2 f0b = *reinterpret_cast<__half2*>(&q.z);
                __half2 dfb = *reinterpret_cast<__half2*>(&q.w);
                LA[d] = __hfma2(w2, dfa, f0a);
                LB[d] = __hfma2(w2, dfb, f0b);
            }
            float2 pa = __half22float2(__hmul2(LA[0], LA[1]));  // half product d0*d1
            float2 pb = __half22float2(__hmul2(LB[0], LB[1]));
            float2 la = __half22float2(LA[2]);                  // third factor
            float2 lb = __half22float2(LB[2]);
            float t0 = pa.x * la.x;
            float t1 = fmaf(pa.y, la.y, t0);
            float t2 = fmaf(pb.x, lb.x, t1);
            accA     = fmaf(pb.y, lb.y, t2);
        }

        // ---- group B ----
        float accB;
        {
            __half2 LA[3], LB[3];
            #pragma unroll
            for (int d = 0; d < 3; d++) {
                uint4 q = tab4[((d * RES + iB[d]) << 3) + (sub ^ (iB[d] & 7))];
                __half2 w2  = __float2half2_rn(wBf[d]);
                __half2 f0a = *reinterpret_cast<__half2*>(&q.x);
                __half2 dfa = *reinterpret_cast<__half2*>(&q.y);
                __half2 f0b = *reinterpret_cast<__half2*>(&q.z);
                __half2 dfb = *reinterpret_cast<__half2*>(&q.w);
                LA[d] = __hfma2(w2, dfa, f0a);
                LB[d] = __hfma2(w2, dfb, f0b);
            }
            float2 pa = __half22float2(__hmul2(LA[0], LA[1]));
            float2 pb = __half22float2(__hmul2(LB[0], LB[1]));
            float2 la = __half22float2(LA[2]);
            float2 lb = __half22float2(LB[2]);
            float t0 = pa.x * la.x;
            float t1 = fmaf(pa.y, la.y, t0);
            float t2 = fmaf(pb.x, lb.x, t1);
            accB     = fmaf(pb.y, lb.y, t2);
        }

        // 3-shfl fused A/B reduction (same tree as before -> bit-identical):
        // exchange the "other" group's partial across xor4, then finish quads.
        {
            float u = (sub < 4) ? accB : accA;
            float t = __shfl_xor_sync(0xffffffffu, u, 4);
            float m = ((sub < 4) ? accA : accB) + t;
            m += __shfl_xor_sync(0xffffffffu, m, 2);
            m += __shfl_xor_sync(0xffffffffu, m, 1);
            if ((sub & 3) == 0)
                out[base + p + (sub & 4)] = m;   // sub==0 -> A, sub==4 -> B
        }

        v = vn;
    }

    // ---- scalar tail: npts % 8 leftover points, handled by warp 0 ----
    const int rem = npts & 7;
    if (rem && gwarp == 0 && lane < rem) {
        int n = (npts & ~7) + lane;
        float acc = 0.0f;
        int   idx[3];
        float wd[3];
        #pragma unroll
        for (int d = 0; d < 3; d++) {
            float x = pts[n * 3 + (2 - d)];
            float pos = fmaf(x, 127.5f, 127.5f);
            int i = __float2int_rd(pos);
            i = min(max(i, 0), RES - 1);
            idx[d] = i;
            wd[d] = pos - (float)i;
        }
        for (int c = 0; c < NCOMP; c++) {
            float prod = 1.0f;
            #pragma unroll
            for (int d = 0; d < 3; d++) {
                int sw = idx[d] & 7;
                int j2 = c >> 1;
                int phys = ((((j2 >> 1) ^ sw) << 1) | (j2 & 1));
                uint2 q = tabu2[(d * RES + idx[d]) * ROWU2 + phys];
                __half2 f0 = *reinterpret_cast<__half2*>(&q.x);
                __half2 df = *reinterpret_cast<__half2*>(&q.y);
                float2 f0f = __half22float2(f0);
                float2 dff = __half22float2(df);
                float a = (c & 1) ? f0f.y : f0f.x;
                float b = (c & 1) ? dff.y : dff.x;
                prod *= fmaf(wd[d], b, a);
            }
            acc += prod;
        }
        out[n] = acc;
    }
}

extern "C" void kernel_launch(void* const* d_in, const int* in_sizes, int n_in,
                              void* d_out, int out_size)
{
    const float* pts  = (const float*)d_in[0];   // [N,3] float32
    const float* coef = (const float*)d_in[1];   // [3,24,256] float32
    float* out = (float*)d_out;

    const int npts = in_sizes[0] / 3;
    const size_t smem = TAB_U2 * sizeof(uint2);  // 98304 B

    cudaFuncSetAttribute(cp_decode_kernel,
                         cudaFuncAttributeMaxDynamicSharedMemorySize,
                         (int)smem);

    cp_decode_kernel<<<NCTAS, THREADS, smem>>>(pts, coef, out, npts);
}

// round 14
// speedup vs baseline: 1.3270x; 1.0149x over previous
#include <cuda_runtime.h>
#include <cuda_fp16.h>

// CPDecoding: out[n] = sum_c prod_d lerp(line_coef[d][c], pos_d(n))
// coords stacked (z,y,x): table dim d uses input column (2-d).
//
// R14 = R12 (LOCKED: 1024 thr x 148 CTAs; fp16 diff table, XOR-swizzled
// 128-B rows -> one conflict-free LDS.128 wavefront per point-dim; coalesced
// swizzled build; HFMA2 lerp + half2 d0*d1 product, fp32 finish; 3-shfl
// fused reduction; pipelined coord loads) + CORRECTED magic floor:
//   R13's fused constant 2^23+127.5 is NOT fp32-representable (ulp@2^23=1)
//   -> silently became 2^23+128 -> garbage. Fix: compute pos = fma(x,127.5,
//   127.5) first (as R12), then t = add.rm(pos, 2^23) which IS exact:
//   i = lowbits(t)&0xFF = floor(pos); w = pos - (t - 2^23), Sterbenz-exact
//   both steps -> w bit-identical to R12's F2I/I2F path, but the two ~20-cyc
//   cross-pipe converts become two 4-cyc fma-pipe ops.
//   + one CVT per dim for both groups' weights (__floats2half2_rn(wA,wB),
//   consumed via __low2half2/__high2half2 half-lane selectors).

#define NCOMP 24
#define RES   256
#define ROWU2 16                        // uint2 slots per row
#define TAB_U2 (3 * RES * ROWU2)        // 12288 uint2 = 98304 B

#define THREADS 1024
#define NCTAS   148

__device__ __forceinline__ float fadd_rm(float a, float b) {
    float r;
    asm("add.rm.f32 %0, %1, %2;" : "=f"(r) : "f"(a), "f"(b));
    return r;
}

__global__ __launch_bounds__(THREADS, 1)
void cp_decode_kernel(const float* __restrict__ pts,
                      const float* __restrict__ coef,
                      float* __restrict__ out,
                      int npts)
{
    extern __shared__ uint2 tabu2[];
    uint4* __restrict__ tabw = reinterpret_cast<uint4*>(tabu2);

    const int tid    = threadIdx.x;
    const int lane   = tid & 31;
    const int wid    = tid >> 5;
    const int gwarp  = (blockIdx.x * THREADS + tid) >> 5;
    const int nwarps = (NCTAS * THREADS) >> 5;
    const int nfull  = npts >> 3;    // full 8-point iterations (all in-bounds)

    // Prologue coord load issued BEFORE the build: latency hidden under it.
    int iter = gwarp;
    float v = 0.0f;
    if (iter < nfull && lane < 24)
        v = __ldg(pts + iter * 24 + lane);

    // ---- Build fp16 diff table: warp-per-(d, 32-row block), coalesced ----
    // Row i: 8 uint4 positions; data slot m (comps 4m..4m+3) at m ^ (i&7).
    if (wid < 24) {
        const int d = wid >> 3;
        const int i = ((wid & 7) << 5) | lane;
        const float* cbase = coef + d * (NCOMP * RES) + i;
        const int ip = (i < RES - 1) ? 1 : 0;
        uint4 s[6];
        #pragma unroll
        for (int h = 0; h < 6; h++) {          // slot h = comps 4h..4h+3
            float a0 = __ldg(cbase + (4 * h + 0) * RES);
            float a1 = __ldg(cbase + (4 * h + 0) * RES + ip);
            float b0 = __ldg(cbase + (4 * h + 1) * RES);
            float b1 = __ldg(cbase + (4 * h + 1) * RES + ip);
            float c0 = __ldg(cbase + (4 * h + 2) * RES);
            float c1 = __ldg(cbase + (4 * h + 2) * RES + ip);
            float e0 = __ldg(cbase + (4 * h + 3) * RES);
            float e1 = __ldg(cbase + (4 * h + 3) * RES + ip);
            __half2 f0x = __floats2half2_rn(a0, b0);
            __half2 dfx = __floats2half2_rn(a1 - a0, b1 - b0);
            __half2 f0y = __floats2half2_rn(c0, e0);
            __half2 dfy = __floats2half2_rn(c1 - c0, e1 - e0);
            s[h].x = *reinterpret_cast<unsigned*>(&f0x);
            s[h].y = *reinterpret_cast<unsigned*>(&dfx);
            s[h].z = *reinterpret_cast<unsigned*>(&f0y);
            s[h].w = *reinterpret_cast<unsigned*>(&dfy);
        }
        uint4* row = tabw + ((d * RES + i) << 3);
        const int sw = i & 7;
        #pragma unroll
        for (int m = 0; m < 6; m++)
            row[m ^ sw] = s[m];
        row[6 ^ sw] = make_uint4(0u, 0u, 0u, 0u);
        row[7 ^ sw] = make_uint4(0u, 0u, 0u, 0u);
    }
    __syncthreads();

    const uint4* __restrict__ tab4 = tabw;

    const int p   = lane >> 3;       // point slot in group of 4
    const int sub = lane & 7;        // lane within point (comps 4sub..4sub+3)

    const float TWO23 = 8388608.0f;  // 2^23, exactly representable

    for (; iter < nfull; iter += nwarps) {
        const int base = iter << 3;

        // Per-dim sample index (magic floor) + packed weights for A/B.
        int     iA[3], iB[3];
        __half2 w2[3];               // (wA, wB) per dim
        #pragma unroll
        for (int d = 0; d < 3; d++) {
            float xA = __shfl_sync(0xffffffffu, v, p * 3 + (2 - d));
            float xB = __shfl_sync(0xffffffffu, v, 12 + p * 3 + (2 - d));
            float posA = fmaf(xA, 127.5f, 127.5f);   // [127.5, 255)
            float posB = fmaf(xB, 127.5f, 127.5f);
            float tA = fadd_rm(posA, TWO23);         // 2^23 + floor(pos)
            float tB = fadd_rm(posB, TWO23);
            iA[d] = __float_as_int(tA) & 0xFF;
            iB[d] = __float_as_int(tB) & 0xFF;
            float wA = posA - (tA - TWO23);          // Sterbenz-exact both steps
            float wB = posB - (tB - TWO23);
            w2[d] = __floats2half2_rn(wA, wB);
        }

        // Prefetch next iteration's coords.
        float vn = 0.0f;
        {
            int itn = iter + nwarps;
            if (itn < nfull && lane < 24)
                vn = __ldg(pts + itn * 24 + lane);
        }

        // ---- group A ----
        float accA;
        {
            __half2 LA[3], LB[3];
            #pragma unroll
            for (int d = 0; d < 3; d++) {
                uint4 q = tab4[((d * RES + iA[d]) << 3) + (sub ^ (iA[d] & 7))];
                __half2 wa  = __low2half2(w2[d]);        // (wA, wA)
                __half2 f0a = *reinterpret_cast<__half2*>(&q.x);
                __half2 dfa = *reinterpret_cast<__half2*>(&q.y);
                __half2 f0b = *reinterpret_cast<__half2*>(&q.z);
                __half2 dfb = *reinterpret_cast<__half2*>(&q.w);
                LA[d] = __hfma2(wa, dfa, f0a);
                LB[d] = __hfma2(wa, dfb, f0b);
            }
            float2 pa = __half22float2(__hmul2(LA[0], LA[1]));  // half d0*d1
            float2 pb = __half22float2(__hmul2(LB[0], LB[1]));
            float2 la = __half22float2(LA[2]);                  // third factor
            float2 lb = __half22float2(LB[2]);
            float t0 = pa.x * la.x;
            float t1 = fmaf(pa.y, la.y, t0);
            float t2 = fmaf(pb.x, lb.x, t1);
            accA     = fmaf(pb.y, lb.y, t2);
        }

        // ---- group B ----
        float accB;
        {
            __half2 LA[3], LB[3];
            #pragma unroll
            for (int d = 0; d < 3; d++) {
                uint4 q = tab4[((d * RES + iB[d]) << 3) + (sub ^ (iB[d] & 7))];
                __half2 wb  = __high2half2(w2[d]);       // (wB, wB)
                __half2 f0a = *reinterpret_cast<__half2*>(&q.x);
                __half2 dfa = *reinterpret_cast<__half2*>(&q.y);
                __half2 f0b = *reinterpret_cast<__half2*>(&q.z);
                __half2 dfb = *reinterpret_cast<__half2*>(&q.w);
                LA[d] = __hfma2(wb, dfa, f0a);
                LB[d] = __hfma2(wb, dfb, f0b);
            }
            float2 pa = __half22float2(__hmul2(LA[0], LA[1]));
            float2 pb = __half22float2(__hmul2(LB[0], LB[1]));
            float2 la = __half22float2(LA[2]);
            float2 lb = __half22float2(LB[2]);
            float t0 = pa.x * la.x;
            float t1 = fmaf(pa.y, la.y, t0);
            float t2 = fmaf(pb.x, lb.x, t1);
            accB     = fmaf(pb.y, lb.y, t2);
        }

        // 3-shfl fused A/B reduction (select-exchange-select).
        {
            float u = (sub < 4) ? accB : accA;
            float t = __shfl_xor_sync(0xffffffffu, u, 4);
            float m = ((sub < 4) ? accA : accB) + t;
            m += __shfl_xor_sync(0xffffffffu, m, 2);
            m += __shfl_xor_sync(0xffffffffu, m, 1);
            if ((sub & 3) == 0)
                out[base + p + (sub & 4)] = m;   // sub==0 -> A, sub==4 -> B
        }

        v = vn;
    }

    // ---- scalar tail: npts % 8 leftover points, handled by warp 0 ----
    const int rem = npts & 7;
    if (rem && gwarp == 0 && lane < rem) {
        int n = (npts & ~7) + lane;
        float acc = 0.0f;
        int   idx[3];
        float wd[3];
        #pragma unroll
        for (int d = 0; d < 3; d++) {
            float x = pts[n * 3 + (2 - d)];
            float pos = fmaf(x, 127.5f, 127.5f);
            int i = __float2int_rd(pos);
            i = min(max(i, 0), RES - 1);
            idx[d] = i;
            wd[d] = pos - (float)i;
        }
        for (int c = 0; c < NCOMP; c++) {
            float prod = 1.0f;
            #pragma unroll
            for (int d = 0; d < 3; d++) {
                int sw = idx[d] & 7;
                int j2 = c >> 1;
                int phys = ((((j2 >> 1) ^ sw) << 1) | (j2 & 1));
                uint2 q = tabu2[(d * RES + idx[d]) * ROWU2 + phys];
                __half2 f0 = *reinterpret_cast<__half2*>(&q.x);
                __half2 df = *reinterpret_cast<__half2*>(&q.y);
                float2 f0f = __half22float2(f0);
                float2 dff = __half22float2(df);
                float a = (c & 1) ? f0f.y : f0f.x;
                float b = (c & 1) ? dff.y : dff.x;
                prod *= fmaf(wd[d], b, a);
            }
            acc += prod;
        }
        out[n] = acc;
    }
}

extern "C" void kernel_launch(void* const* d_in, const int* in_sizes, int n_in,
                              void* d_out, int out_size)
{
    const float* pts  = (const float*)d_in[0];   // [N,3] float32
    const float* coef = (const float*)d_in[1];   // [3,24,256] float32
    float* out = (float*)d_out;

    const int npts = in_sizes[0] / 3;
    const size_t smem = TAB_U2 * sizeof(uint2);  // 98304 B

    cudaFuncSetAttribute(cp_decode_kernel,
                         cudaFuncAttributeMaxDynamicSharedMemorySize,
                         (int)smem);

    cp_decode_kernel<<<NCTAS, THREADS, smem>>>(pts, coef, out, npts);
}